// round 4
// baseline (speedup 1.0000x reference)
#include <cuda_runtime.h>
#include <cuda_bf16.h>
#include <math.h>

#define NB     128
#define SLEN   1024
#define INF_   768
#define EMB    512
#define NSPLIT 8
#define CHUNK  (SLEN / NSPLIT)   // 128
#define TS     16                // tokens per smem tile in flash pass
#define FLASH_SMEM ((8*512 + TS*512 + 8) * 4)  // qWs + tile + qbs = 49184 B

// -------- scratch (device globals; zero-init, no runtime allocation) --------
__device__ float g_x[1536 * 512];            // fc1 out, [N*12, 512]
__device__ float g_fc2part[8 * 128 * 512];   // split-K partials
__device__ float g_vfeat[128 * 512];
__device__ float g_q[128 * 512];             // scaled q (+bq)
__device__ float g_qW[128 * 8 * 512];        // per-head q projected through Wk
__device__ float g_qb[128 * 8];              // q . bk per head
__device__ float g_ml[128 * 8 * 8 * 2];      // (m,l) per (n,chunk,head)
__device__ float g_acc[128 * 8 * 8 * 512];   // flash accumulators
__device__ float g_u[128 * 8 * 512];         // normalized weighted sum of t
__device__ float g_ctx[128 * 512];

// ============ fc1: g_x = relu(V[1536,768] @ W1[512,768]^T + b1) ============
__global__ void fc1_kernel(const float* __restrict__ A, const float* __restrict__ B,
                           const float* __restrict__ bias)
{
    __shared__ float As[16][68];
    __shared__ float Bs[16][68];
    const int m0 = blockIdx.x * 64, n0 = blockIdx.y * 64;
    const int tid = threadIdx.x;
    const int lr = tid >> 2, lc = (tid & 3) << 2;
    const int tx = tid & 15, ty = tid >> 4;
    float acc[4][4] = {};
    for (int k0 = 0; k0 < INF_; k0 += 16) {
        float4 a4 = *(const float4*)(A + (m0 + lr) * INF_ + k0 + lc);
        float4 b4 = *(const float4*)(B + (n0 + lr) * INF_ + k0 + lc);
        As[lc+0][lr] = a4.x; As[lc+1][lr] = a4.y; As[lc+2][lr] = a4.z; As[lc+3][lr] = a4.w;
        Bs[lc+0][lr] = b4.x; Bs[lc+1][lr] = b4.y; Bs[lc+2][lr] = b4.z; Bs[lc+3][lr] = b4.w;
        __syncthreads();
#pragma unroll
        for (int k = 0; k < 16; k++) {
            float4 ar = *(const float4*)&As[k][ty * 4];
            float4 br = *(const float4*)&Bs[k][tx * 4];
            float arr[4] = {ar.x, ar.y, ar.z, ar.w};
            float brr[4] = {br.x, br.y, br.z, br.w};
#pragma unroll
            for (int i = 0; i < 4; i++)
#pragma unroll
                for (int j = 0; j < 4; j++) acc[i][j] = fmaf(arr[i], brr[j], acc[i][j]);
        }
        __syncthreads();
    }
#pragma unroll
    for (int i = 0; i < 4; i++)
#pragma unroll
        for (int j = 0; j < 4; j++) {
            float v = acc[i][j] + bias[n0 + tx * 4 + j];
            g_x[(m0 + ty * 4 + i) * 512 + n0 + tx * 4 + j] = fmaxf(v, 0.f);
        }
}

// ===== fc2 split-K: part[z] = X[128, z-th 768 of 6144] @ W2[512,6144]^T =====
__global__ void fc2_kernel(const float* __restrict__ B)
{
    __shared__ float As[16][68];
    __shared__ float Bs[16][68];
    const int m0 = blockIdx.x * 64, n0 = blockIdx.y * 64, z = blockIdx.z;
    const int tid = threadIdx.x;
    const int lr = tid >> 2, lc = (tid & 3) << 2;
    const int tx = tid & 15, ty = tid >> 4;
    const int kbeg = z * 768, kend = kbeg + 768;
    float acc[4][4] = {};
    for (int k0 = kbeg; k0 < kend; k0 += 16) {
        float4 a4 = *(const float4*)(g_x + (m0 + lr) * 6144 + k0 + lc);
        float4 b4 = *(const float4*)(B + (n0 + lr) * 6144 + k0 + lc);
        As[lc+0][lr] = a4.x; As[lc+1][lr] = a4.y; As[lc+2][lr] = a4.z; As[lc+3][lr] = a4.w;
        Bs[lc+0][lr] = b4.x; Bs[lc+1][lr] = b4.y; Bs[lc+2][lr] = b4.z; Bs[lc+3][lr] = b4.w;
        __syncthreads();
#pragma unroll
        for (int k = 0; k < 16; k++) {
            float4 ar = *(const float4*)&As[k][ty * 4];
            float4 br = *(const float4*)&Bs[k][tx * 4];
            float arr[4] = {ar.x, ar.y, ar.z, ar.w};
            float brr[4] = {br.x, br.y, br.z, br.w};
#pragma unroll
            for (int i = 0; i < 4; i++)
#pragma unroll
                for (int j = 0; j < 4; j++) acc[i][j] = fmaf(arr[i], brr[j], acc[i][j]);
        }
        __syncthreads();
    }
#pragma unroll
    for (int i = 0; i < 4; i++)
#pragma unroll
        for (int j = 0; j < 4; j++)
            g_fc2part[z * 65536 + (m0 + ty * 4 + i) * 512 + n0 + tx * 4 + j] = acc[i][j];
}

__global__ void fc2_reduce(const float* __restrict__ bias, float* __restrict__ dout)
{
    int i = blockIdx.x * 256 + threadIdx.x;   // 65536 total
    float s = bias[i & 511];
#pragma unroll
    for (int z = 0; z < 8; z++) s += g_fc2part[z * 65536 + i];
    s = fmaxf(s, 0.f);
    g_vfeat[i] = s;
    dout[i] = s;
}

// ======== small GEMM: M up to 128, 32x32 tiles, 64 threads, 4x4/thread ========
// MODE 0: q   = (vfeat @ Wq^T + bq) * 0.125              [128,512]
// MODE 1: ctx = u_h @ Wv_h^T + bv_h   (per head z)       [128,64]
// MODE 2: out = ctx @ Wo^T + bo  -> Cext                 [128,512]
// MODE 3: qW_h = q_h @ Wk_h  (B direct, per head z)      [128,512]
template <int MODE>
__global__ void gemm32(const float* __restrict__ Bw, const float* __restrict__ bias,
                       float* __restrict__ Cext)
{
    constexpr int K   = (MODE == 3) ? 64 : 512;
    constexpr bool BT = (MODE != 3);
    const int z = blockIdx.z;
    const float* A; float* C; int lda, ldc; const float* bp = bias;
    const float* B = Bw;
    if (MODE == 0) { A = g_vfeat;       lda = 512;  C = g_q;            ldc = 512; }
    if (MODE == 1) { A = g_u + z * 512; lda = 4096; C = g_ctx + z * 64; ldc = 512;
                     B = Bw + z * (64 * 512); bp = bias + z * 64; }
    if (MODE == 2) { A = g_ctx;         lda = 512;  C = Cext;           ldc = 512; }
    if (MODE == 3) { A = g_q + z * 64;  lda = 512;  C = g_qW + z * 512; ldc = 4096;
                     B = Bw + z * (64 * 512); }

    __shared__ float As[32][36];
    __shared__ float Bs[32][36];
    const int m0 = blockIdx.x * 32, n0 = blockIdx.y * 32;
    const int tid = threadIdx.x;             // 64 threads
    const int tx = tid & 7, ty = tid >> 3;
    float acc[4][4] = {};
    for (int k0 = 0; k0 < K; k0 += 32) {
        for (int i = tid; i < 256; i += 64) {
            int row = i >> 3, c4 = (i & 7) << 2;
            float4 a4 = *(const float4*)(A + (m0 + row) * lda + k0 + c4);
            As[c4+0][row] = a4.x; As[c4+1][row] = a4.y;
            As[c4+2][row] = a4.z; As[c4+3][row] = a4.w;
            if (BT) {
                float4 b4 = *(const float4*)(B + (n0 + row) * 512 + k0 + c4);
                Bs[c4+0][row] = b4.x; Bs[c4+1][row] = b4.y;
                Bs[c4+2][row] = b4.z; Bs[c4+3][row] = b4.w;
            } else {
                float4 b4 = *(const float4*)(B + (k0 + row) * 512 + n0 + c4);
                *(float4*)&Bs[row][c4] = b4;
            }
        }
        __syncthreads();
#pragma unroll
        for (int k = 0; k < 32; k++) {
            float4 ar = *(const float4*)&As[k][ty * 4];
            float4 br = *(const float4*)&Bs[k][tx * 4];
            float arr[4] = {ar.x, ar.y, ar.z, ar.w};
            float brr[4] = {br.x, br.y, br.z, br.w};
#pragma unroll
            for (int i = 0; i < 4; i++)
#pragma unroll
                for (int j = 0; j < 4; j++) acc[i][j] = fmaf(arr[i], brr[j], acc[i][j]);
        }
        __syncthreads();
    }
#pragma unroll
    for (int i = 0; i < 4; i++)
#pragma unroll
        for (int j = 0; j < 4; j++) {
            float v = acc[i][j];
            if (MODE == 0) v = (v + bp[n0 + tx * 4 + j]) * 0.125f;
            if (MODE == 1 || MODE == 2) v = v + bp[n0 + tx * 4 + j];
            C[(m0 + ty * 4 + i) * ldc + n0 + tx * 4 + j] = v;
        }
}

// qb[n,h] = q[n,h,:] . bk[h,:]
__global__ void qb_kernel(const float* __restrict__ bk)
{
    int t = blockIdx.x * 256 + threadIdx.x;
    if (t < 1024) {
        int n = t >> 3, h = t & 7;
        float s = 0.f;
#pragma unroll 16
        for (int d = 0; d < 64; d++) s = fmaf(g_q[n * 512 + h * 64 + d], bk[h * 64 + d], s);
        g_qb[t] = s;
    }
}

// ====== flash pass: scores + online softmax + weighted-t accumulation ======
// grid (NSPLIT, N), 128 threads. Warp w handles heads w and w+4.
__global__ void __launch_bounds__(128)
flash_kernel(const float* __restrict__ T, const int* __restrict__ t_len)
{
    extern __shared__ float sm[];
    float* qWs = sm;                 // 8*512
    float* tile = sm + 4096;         // TS*512
    float* qbs = sm + 4096 + TS*512; // 8
    const int n = blockIdx.y, ck = blockIdx.x;
    const int tid = threadIdx.x, warp = tid >> 5, lane = tid & 31;
    const int len = t_len[n];
    const int s0 = ck * CHUNK;
    const int ob = (n * NSPLIT + ck) * 8;
    if (s0 >= len) {
        if (tid < 8) { g_ml[2*(ob+tid)] = -INFINITY; g_ml[2*(ob+tid)+1] = 0.f; }
        return;
    }
    const int s1 = min(s0 + CHUNK, len);

    for (int i = tid; i < 4096; i += 128) qWs[i] = g_qW[n * 4096 + i];
    if (tid < 8) qbs[tid] = g_qb[n * 8 + tid];
    __syncthreads();

    const int h0 = warp, h1 = warp + 4;
    float qr0[16], qr1[16];
#pragma unroll
    for (int j = 0; j < 4; j++) {
        float4 v0 = *(const float4*)&qWs[h0 * 512 + lane * 16 + j * 4];
        float4 v1 = *(const float4*)&qWs[h1 * 512 + lane * 16 + j * 4];
        qr0[j*4+0]=v0.x; qr0[j*4+1]=v0.y; qr0[j*4+2]=v0.z; qr0[j*4+3]=v0.w;
        qr1[j*4+0]=v1.x; qr1[j*4+1]=v1.y; qr1[j*4+2]=v1.z; qr1[j*4+3]=v1.w;
    }
    const float qb0 = qbs[h0], qb1 = qbs[h1];
    float acc0[16], acc1[16];
#pragma unroll
    for (int i = 0; i < 16; i++) { acc0[i] = 0.f; acc1[i] = 0.f; }
    float m0v = -INFINITY, l0v = 0.f, m1v = -INFINITY, l1v = 0.f;

    for (int s = s0; s < s1; s += TS) {
        const int c = min(TS, s1 - s);
        __syncthreads();
        {
            const float4* src = (const float4*)(T + ((size_t)n * SLEN + s) * 512);
            float4* dst = (float4*)tile;
            for (int i = tid; i < c * 128; i += 128) dst[i] = src[i];
        }
        __syncthreads();
        for (int ts = 0; ts < c; ts++) {
            float tv[16];
            const float* tr = tile + ts * 512;
#pragma unroll
            for (int j = 0; j < 4; j++) {
                float4 v = *(const float4*)&tr[lane * 16 + j * 4];
                tv[j*4+0]=v.x; tv[j*4+1]=v.y; tv[j*4+2]=v.z; tv[j*4+3]=v.w;
            }
            float p0 = 0.f, p1 = 0.f;
#pragma unroll
            for (int i = 0; i < 16; i++) { p0 = fmaf(qr0[i], tv[i], p0); p1 = fmaf(qr1[i], tv[i], p1); }
#pragma unroll
            for (int o = 16; o; o >>= 1) {
                p0 += __shfl_xor_sync(0xffffffffu, p0, o);
                p1 += __shfl_xor_sync(0xffffffffu, p1, o);
            }
            p0 += qb0; p1 += qb1;
            if (p0 > m0v) {
                float r = __expf(m0v - p0); m0v = p0; l0v = fmaf(l0v, r, 1.f);
#pragma unroll
                for (int i = 0; i < 16; i++) acc0[i] = fmaf(acc0[i], r, tv[i]);
            } else {
                float e = __expf(p0 - m0v); l0v += e;
#pragma unroll
                for (int i = 0; i < 16; i++) acc0[i] = fmaf(e, tv[i], acc0[i]);
            }
            if (p1 > m1v) {
                float r = __expf(m1v - p1); m1v = p1; l1v = fmaf(l1v, r, 1.f);
#pragma unroll
                for (int i = 0; i < 16; i++) acc1[i] = fmaf(acc1[i], r, tv[i]);
            } else {
                float e = __expf(p1 - m1v); l1v += e;
#pragma unroll
                for (int i = 0; i < 16; i++) acc1[i] = fmaf(e, tv[i], acc1[i]);
            }
        }
    }
    if (lane == 0) {
        g_ml[2*(ob+h0)] = m0v; g_ml[2*(ob+h0)+1] = l0v;
        g_ml[2*(ob+h1)] = m1v; g_ml[2*(ob+h1)+1] = l1v;
    }
    float* a0 = g_acc + (size_t)(ob + h0) * 512;
    float* a1 = g_acc + (size_t)(ob + h1) * 512;
#pragma unroll
    for (int j = 0; j < 4; j++) {
        *(float4*)&a0[lane*16 + j*4] = make_float4(acc0[j*4], acc0[j*4+1], acc0[j*4+2], acc0[j*4+3]);
        *(float4*)&a1[lane*16 + j*4] = make_float4(acc1[j*4], acc1[j*4+1], acc1[j*4+2], acc1[j*4+3]);
    }
}

// ====== combine: log-sum-exp merge of 8 chunks -> g_u[n,h,512] ======
__global__ void combine_kernel()
{
    const int b = blockIdx.x;       // n*8 + h
    const int n = b >> 3, h = b & 7;
    float mv[8], lv[8];
    float M = -INFINITY;
#pragma unroll
    for (int c = 0; c < 8; c++) {
        int idx = (n * 8 + c) * 8 + h;
        mv[c] = g_ml[2*idx]; lv[c] = g_ml[2*idx+1];
        M = fmaxf(M, mv[c]);
    }
    float w[8], L = 0.f;
#pragma unroll
    for (int c = 0; c < 8; c++) {
        w[c] = (mv[c] == -INFINITY) ? 0.f : __expf(mv[c] - M);
        L = fmaf(w[c], lv[c], L);
    }
    const float invL = 1.f / L;
    const int d0 = threadIdx.x * 4;
    float4 s = make_float4(0.f, 0.f, 0.f, 0.f);
#pragma unroll
    for (int c = 0; c < 8; c++) {
        if (w[c] != 0.f) {
            float4 a = *(const float4*)&g_acc[(size_t)((n*8+c)*8+h) * 512 + d0];
            s.x = fmaf(w[c], a.x, s.x); s.y = fmaf(w[c], a.y, s.y);
            s.z = fmaf(w[c], a.z, s.z); s.w = fmaf(w[c], a.w, s.w);
        }
    }
    s.x *= invL; s.y *= invL; s.z *= invL; s.w *= invL;
    *(float4*)&g_u[(size_t)(n*8+h) * 512 + d0] = s;
}

extern "C" void kernel_launch(void* const* d_in, const int* in_sizes, int n_in,
                              void* d_out, int out_size)
{
    const float* v     = (const float*)d_in[0];
    const float* t     = (const float*)d_in[1];
    const int*   t_len = (const int*)  d_in[2];
    const float* W_fc1 = (const float*)d_in[3];
    const float* b_fc1 = (const float*)d_in[4];
    const float* W_fc2 = (const float*)d_in[5];
    const float* b_fc2 = (const float*)d_in[6];
    const float* Wq    = (const float*)d_in[7];
    const float* Wk    = (const float*)d_in[8];
    const float* Wv    = (const float*)d_in[9];
    const float* bq    = (const float*)d_in[10];
    const float* bk    = (const float*)d_in[11];
    const float* bv    = (const float*)d_in[12];
    const float* Wo    = (const float*)d_in[13];
    const float* bo    = (const float*)d_in[14];
    float* out = (float*)d_out;

    fc1_kernel<<<dim3(24, 8), 256>>>(v, W_fc1, b_fc1);
    fc2_kernel<<<dim3(2, 8, 8), 256>>>(W_fc2);
    fc2_reduce<<<256, 256>>>(b_fc2, out);                 // vfeat -> out[0:65536]
    gemm32<0><<<dim3(4, 16, 1), 64>>>(Wq, bq, nullptr);   // q
    qb_kernel<<<4, 256>>>(bk);
    gemm32<3><<<dim3(4, 16, 8), 64>>>(Wk, nullptr, nullptr); // qW per head
    cudaFuncSetAttribute(flash_kernel, cudaFuncAttributeMaxDynamicSharedMemorySize, FLASH_SMEM);
    flash_kernel<<<dim3(NSPLIT, NB), 128, FLASH_SMEM>>>(t, t_len);
    combine_kernel<<<1024, 128>>>();
    gemm32<1><<<dim3(4, 2, 8), 64>>>(Wv, bv, nullptr);    // ctx per head
    gemm32<2><<<dim3(4, 16, 1), 64>>>(Wo, bo, out + 65536); // attn_out -> out[65536:]
}

// round 6
// speedup vs baseline: 1.0900x; 1.0900x over previous
#include <cuda_runtime.h>
#include <cuda_bf16.h>
#include <math.h>

#define NB     128
#define SLEN   1024
#define INF_   768
#define EMB    512
#define NSPLIT 8
#define CHUNK  (SLEN / NSPLIT)   // 128
#define TS     16                // tokens per smem tile in flash pass
#define FLASH_SMEM ((8*512 + TS*512 + 8) * 4)  // 49184 B
#define SCALE  0.125f            // 1/sqrt(64)

// -------- scratch (device globals; no runtime allocation) --------
__device__ float g_x[1536 * 512];            // fc1 out
__device__ float g_fc2part[8 * 128 * 512];   // split-K partials (reused for out GEMM)
__device__ float g_vfeat[128 * 512];
__device__ float g_qW[128 * 4096];           // per-head q projected through Wk
__device__ float g_qb[128 * 8];
__device__ float g_ml[128 * 8 * 8 * 2];
__device__ float g_acc[128 * 8 * 8 * 512];
__device__ float g_u[128 * 4096];            // normalized weighted sum of t
// weight-only precomputes
__device__ float g_wqT[512 * 512];
__device__ float g_wvT[512 * 512];
__device__ float g_woT[512 * 512];
__device__ float g_wqk[512 * 4096];          // [i, h*512+j]
__device__ float g_wvo[4096 * 512];          // [h*512+dt, e]
__device__ float g_qwb[8 * 512];             // scale * bq_h . Wk_h[:,j]
__device__ float g_wqb[8 * 512];             // scale * Wq_h^T bk_h
__device__ float g_cq[8];                    // scale * bq_h . bk_h
__device__ float g_bout[512];                // bo + Wo @ bv

// ============ 512x512 transpose ============
__global__ void transpose512(const float* __restrict__ A, float* __restrict__ At)
{
    __shared__ float s[32][33];
    const int x0 = blockIdx.x * 32, y0 = blockIdx.y * 32;
    const int tx = threadIdx.x, ty = threadIdx.y;   // 32 x 8
#pragma unroll
    for (int i = 0; i < 32; i += 8) s[ty + i][tx] = A[(y0 + ty + i) * 512 + x0 + tx];
    __syncthreads();
#pragma unroll
    for (int i = 0; i < 32; i += 8) At[(x0 + ty + i) * 512 + y0 + tx] = s[tx][ty + i];
}

// ===== per-head prep GEMM: C = scale * A[:, h*64:]^chunk @ B[h*64:, :] (K=64) =====
// A row-major [512,512] (uses cols h*64..h*64+63); B row-major (rows h*64..).
// C addr = (rowOff*h + m)*ldc + colOff*h + n
__global__ void prep_gemm(const float* __restrict__ A, const float* __restrict__ B,
                          float* __restrict__ C, int ldc, int rowOff, int colOff, float scale)
{
    __shared__ float As[16][72];
    __shared__ float Bs[16][72];
    const int h = blockIdx.z;
    const int m0 = blockIdx.x * 64, n0 = blockIdx.y * 64;
    const int tid = threadIdx.x;
    const int lrA = tid >> 2, lcA = (tid & 3) << 2;     // 64 rows(m) x 16 k
    const int lrB = tid >> 4, lcB = (tid & 15) << 2;    // 16 rows(k) x 64 n
    const int tx = tid & 15, ty = tid >> 4;
    float acc[4][4] = {};
    for (int k0 = 0; k0 < 64; k0 += 16) {
        float4 a4 = *(const float4*)(A + (m0 + lrA) * 512 + h * 64 + k0 + lcA);
        As[lcA+0][lrA] = a4.x; As[lcA+1][lrA] = a4.y; As[lcA+2][lrA] = a4.z; As[lcA+3][lrA] = a4.w;
        *(float4*)&Bs[lrB][lcB] = *(const float4*)(B + (h * 64 + k0 + lrB) * 512 + n0 + lcB);
        __syncthreads();
#pragma unroll
        for (int k = 0; k < 16; k++) {
            float4 ar = *(const float4*)&As[k][ty * 4];
            float4 br = *(const float4*)&Bs[k][tx * 4];
            float arr[4] = {ar.x, ar.y, ar.z, ar.w};
            float brr[4] = {br.x, br.y, br.z, br.w};
#pragma unroll
            for (int i = 0; i < 4; i++)
#pragma unroll
                for (int j = 0; j < 4; j++) acc[i][j] = fmaf(arr[i], brr[j], acc[i][j]);
        }
        __syncthreads();
    }
#pragma unroll
    for (int i = 0; i < 4; i++)
#pragma unroll
        for (int j = 0; j < 4; j++)
            C[(rowOff * h + m0 + ty * 4 + i) * ldc + colOff * h + n0 + tx * 4 + j] = scale * acc[i][j];
}

// ===== misc weight preps: qwb, wqb, bout, cq =====
__global__ void misc_prep(const float* __restrict__ Wq, const float* __restrict__ Wk,
                          const float* __restrict__ Wo, const float* __restrict__ bq,
                          const float* __restrict__ bk, const float* __restrict__ bv,
                          const float* __restrict__ bo)
{
    const int idx = blockIdx.x * 256 + threadIdx.x;
    if (idx < 4096) {                       // qwb[h,j] = scale * sum_e bq[h64+e] Wk[h64+e, j]
        const int h = idx >> 9, j = idx & 511;
        float s = 0.f;
#pragma unroll 8
        for (int e = 0; e < 64; e++) s = fmaf(bq[h * 64 + e], Wk[(h * 64 + e) * 512 + j], s);
        g_qwb[idx] = SCALE * s;
    } else if (idx < 8192) {                // wqb[h,i] = scale * sum_e Wq[h64+e, i] bk[h64+e]
        const int t = idx - 4096, h = t >> 9, i = t & 511;
        float s = 0.f;
#pragma unroll 8
        for (int e = 0; e < 64; e++) s = fmaf(Wq[(h * 64 + e) * 512 + i], bk[h * 64 + e], s);
        g_wqb[t] = SCALE * s;
    } else if (idx < 8704) {                // bout[e] = bo[e] + Wo[e,:] . bv
        const int e = idx - 8192;
        float s = bo[e];
        for (int j = 0; j < 512; j += 4) {
            float4 w = *(const float4*)(Wo + e * 512 + j);
            float4 b = *(const float4*)(bv + j);
            s = fmaf(w.x, b.x, s); s = fmaf(w.y, b.y, s);
            s = fmaf(w.z, b.z, s); s = fmaf(w.w, b.w, s);
        }
        g_bout[e] = s;
    } else if (idx < 8712) {                // cq[h] = scale * bq_h . bk_h
        const int h = idx - 8704;
        float s = 0.f;
#pragma unroll 8
        for (int e = 0; e < 64; e++) s = fmaf(bq[h * 64 + e], bk[h * 64 + e], s);
        g_cq[h] = SCALE * s;
    }
}

// ============ fc1: g_x = relu(V[1536,768] @ W1[512,768]^T + b1) ============
__global__ void fc1_kernel(const float* __restrict__ A, const float* __restrict__ B,
                           const float* __restrict__ bias)
{
    __shared__ float As[16][68];
    __shared__ float Bs[16][68];
    const int m0 = blockIdx.x * 64, n0 = blockIdx.y * 64;
    const int tid = threadIdx.x;
    const int lr = tid >> 2, lc = (tid & 3) << 2;
    const int tx = tid & 15, ty = tid >> 4;
    float acc[4][4] = {};
    for (int k0 = 0; k0 < INF_; k0 += 16) {
        float4 a4 = *(const float4*)(A + (m0 + lr) * INF_ + k0 + lc);
        float4 b4 = *(const float4*)(B + (n0 + lr) * INF_ + k0 + lc);
        As[lc+0][lr] = a4.x; As[lc+1][lr] = a4.y; As[lc+2][lr] = a4.z; As[lc+3][lr] = a4.w;
        Bs[lc+0][lr] = b4.x; Bs[lc+1][lr] = b4.y; Bs[lc+2][lr] = b4.z; Bs[lc+3][lr] = b4.w;
        __syncthreads();
#pragma unroll
        for (int k = 0; k < 16; k++) {
            float4 ar = *(const float4*)&As[k][ty * 4];
            float4 br = *(const float4*)&Bs[k][tx * 4];
            float arr[4] = {ar.x, ar.y, ar.z, ar.w};
            float brr[4] = {br.x, br.y, br.z, br.w};
#pragma unroll
            for (int i = 0; i < 4; i++)
#pragma unroll
                for (int j = 0; j < 4; j++) acc[i][j] = fmaf(arr[i], brr[j], acc[i][j]);
        }
        __syncthreads();
    }
#pragma unroll
    for (int i = 0; i < 4; i++)
#pragma unroll
        for (int j = 0; j < 4; j++) {
            float v = acc[i][j] + bias[n0 + tx * 4 + j];
            g_x[(m0 + ty * 4 + i) * 512 + n0 + tx * 4 + j] = fmaxf(v, 0.f);
        }
}

// ===== fc2 split-K: part[z] = X[128, z-th 768 of 6144] @ W2[512,6144]^T =====
__global__ void fc2_kernel(const float* __restrict__ B)
{
    __shared__ float As[16][68];
    __shared__ float Bs[16][68];
    const int m0 = blockIdx.x * 64, n0 = blockIdx.y * 64, z = blockIdx.z;
    const int tid = threadIdx.x;
    const int lr = tid >> 2, lc = (tid & 3) << 2;
    const int tx = tid & 15, ty = tid >> 4;
    const int kbeg = z * 768, kend = kbeg + 768;
    float acc[4][4] = {};
    for (int k0 = kbeg; k0 < kend; k0 += 16) {
        float4 a4 = *(const float4*)(g_x + (m0 + lr) * 6144 + k0 + lc);
        float4 b4 = *(const float4*)(B + (n0 + lr) * 6144 + k0 + lc);
        As[lc+0][lr] = a4.x; As[lc+1][lr] = a4.y; As[lc+2][lr] = a4.z; As[lc+3][lr] = a4.w;
        Bs[lc+0][lr] = b4.x; Bs[lc+1][lr] = b4.y; Bs[lc+2][lr] = b4.z; Bs[lc+3][lr] = b4.w;
        __syncthreads();
#pragma unroll
        for (int k = 0; k < 16; k++) {
            float4 ar = *(const float4*)&As[k][ty * 4];
            float4 br = *(const float4*)&Bs[k][tx * 4];
            float arr[4] = {ar.x, ar.y, ar.z, ar.w};
            float brr[4] = {br.x, br.y, br.z, br.w};
#pragma unroll
            for (int i = 0; i < 4; i++)
#pragma unroll
                for (int j = 0; j < 4; j++) acc[i][j] = fmaf(arr[i], brr[j], acc[i][j]);
        }
        __syncthreads();
    }
#pragma unroll
    for (int i = 0; i < 4; i++)
#pragma unroll
        for (int j = 0; j < 4; j++)
            g_fc2part[z * 65536 + (m0 + ty * 4 + i) * 512 + n0 + tx * 4 + j] = acc[i][j];
}

__global__ void fc2_reduce(const float* __restrict__ bias, float* __restrict__ dout)
{
    int i = blockIdx.x * 256 + threadIdx.x;
    float s = bias[i & 511];
#pragma unroll
    for (int z = 0; z < 8; z++) s += g_fc2part[z * 65536 + i];
    s = fmaxf(s, 0.f);
    g_vfeat[i] = s;
    dout[i] = s;
}

// ===== qW = vfeat[128,512] @ Wqk[512,4096] + qwb   (M=128,N=4096,K=512) =====
__global__ void qw_kernel()
{
    __shared__ float As[16][72];
    __shared__ float Bs[16][72];
    const int m0 = blockIdx.x * 64, n0 = blockIdx.y * 64;
    const int tid = threadIdx.x;
    const int lrA = tid >> 2, lcA = (tid & 3) << 2;
    const int lrB = tid >> 4, lcB = (tid & 15) << 2;
    const int tx = tid & 15, ty = tid >> 4;
    float acc[4][4] = {};
    for (int k0 = 0; k0 < 512; k0 += 16) {
        float4 a4 = *(const float4*)(g_vfeat + (m0 + lrA) * 512 + k0 + lcA);
        As[lcA+0][lrA] = a4.x; As[lcA+1][lrA] = a4.y; As[lcA+2][lrA] = a4.z; As[lcA+3][lrA] = a4.w;
        *(float4*)&Bs[lrB][lcB] = *(const float4*)(g_wqk + (size_t)(k0 + lrB) * 4096 + n0 + lcB);
        __syncthreads();
#pragma unroll
        for (int k = 0; k < 16; k++) {
            float4 ar = *(const float4*)&As[k][ty * 4];
            float4 br = *(const float4*)&Bs[k][tx * 4];
            float arr[4] = {ar.x, ar.y, ar.z, ar.w};
            float brr[4] = {br.x, br.y, br.z, br.w};
#pragma unroll
            for (int i = 0; i < 4; i++)
#pragma unroll
                for (int j = 0; j < 4; j++) acc[i][j] = fmaf(arr[i], brr[j], acc[i][j]);
        }
        __syncthreads();
    }
#pragma unroll
    for (int i = 0; i < 4; i++)
#pragma unroll
        for (int j = 0; j < 4; j++) {
            int col = n0 + tx * 4 + j;
            g_qW[(size_t)(m0 + ty * 4 + i) * 4096 + col] = acc[i][j] + g_qwb[col];
        }
}

// ===== qb[n,h] = vfeat[n] . wqb[h] + cq[h]  (warp per dot) =====
__global__ void qb2_kernel()
{
    const int w = (blockIdx.x * blockDim.x + threadIdx.x) >> 5;   // 0..1023
    const int lane = threadIdx.x & 31;
    const int n = w >> 3, h = w & 7;
    float s = 0.f;
#pragma unroll
    for (int j = 0; j < 4; j++) {
        float4 a = *(const float4*)(g_vfeat + n * 512 + lane * 16 + j * 4);
        float4 b = *(const float4*)(g_wqb + h * 512 + lane * 16 + j * 4);
        s = fmaf(a.x, b.x, s); s = fmaf(a.y, b.y, s);
        s = fmaf(a.z, b.z, s); s = fmaf(a.w, b.w, s);
    }
#pragma unroll
    for (int o = 16; o; o >>= 1) s += __shfl_xor_sync(0xffffffffu, s, o);
    if (lane == 0) g_qb[n * 8 + h] = s + g_cq[h];
}

// ====== flash pass: scores + online softmax + weighted-t accumulation ======
__global__ void __launch_bounds__(128)
flash_kernel(const float* __restrict__ T, const int* __restrict__ t_len)
{
    extern __shared__ float sm[];
    float* qWs = sm;
    float* tile = sm + 4096;
    float* qbs = sm + 4096 + TS * 512;
    const int n = blockIdx.y, ck = blockIdx.x;
    const int tid = threadIdx.x, warp = tid >> 5, lane = tid & 31;
    const int len = t_len[n];
    const int s0 = ck * CHUNK;
    const int ob = (n * NSPLIT + ck) * 8;
    if (s0 >= len) {
        if (tid < 8) { g_ml[2*(ob+tid)] = -INFINITY; g_ml[2*(ob+tid)+1] = 0.f; }
        return;
    }
    const int s1 = min(s0 + CHUNK, len);

    for (int i = tid; i < 4096; i += 128) qWs[i] = g_qW[(size_t)n * 4096 + i];
    if (tid < 8) qbs[tid] = g_qb[n * 8 + tid];
    __syncthreads();

    const int h0 = warp, h1 = warp + 4;
    float qr0[16], qr1[16];
#pragma unroll
    for (int j = 0; j < 4; j++) {
        float4 v0 = *(const float4*)&qWs[h0 * 512 + lane * 16 + j * 4];
        float4 v1 = *(const float4*)&qWs[h1 * 512 + lane * 16 + j * 4];
        qr0[j*4+0]=v0.x; qr0[j*4+1]=v0.y; qr0[j*4+2]=v0.z; qr0[j*4+3]=v0.w;
        qr1[j*4+0]=v1.x; qr1[j*4+1]=v1.y; qr1[j*4+2]=v1.z; qr1[j*4+3]=v1.w;
    }
    const float qb0 = qbs[h0], qb1 = qbs[h1];
    float acc0[16], acc1[16];
#pragma unroll
    for (int i = 0; i < 16; i++) { acc0[i] = 0.f; acc1[i] = 0.f; }
    float m0v = -INFINITY, l0v = 0.f, m1v = -INFINITY, l1v = 0.f;

    for (int s = s0; s < s1; s += TS) {
        const int c = min(TS, s1 - s);
        __syncthreads();
        {
            const float4* src = (const float4*)(T + ((size_t)n * SLEN + s) * 512);
            float4* dst = (float4*)tile;
            for (int i = tid; i < c * 128; i += 128) dst[i] = src[i];
        }
        __syncthreads();
        for (int ts = 0; ts < c; ts++) {
            float tv[16];
            const float* tr = tile + ts * 512;
#pragma unroll
            for (int j = 0; j < 4; j++) {
                float4 v = *(const float4*)&tr[lane * 16 + j * 4];
                tv[j*4+0]=v.x; tv[j*4+1]=v.y; tv[j*4+2]=v.z; tv[j*4+3]=v.w;
            }
            float p0 = 0.f, p1 = 0.f;
#pragma unroll
            for (int i = 0; i < 16; i++) { p0 = fmaf(qr0[i], tv[i], p0); p1 = fmaf(qr1[i], tv[i], p1); }
#pragma unroll
            for (int o = 16; o; o >>= 1) {
                p0 += __shfl_xor_sync(0xffffffffu, p0, o);
                p1 += __shfl_xor_sync(0xffffffffu, p1, o);
            }
            p0 += qb0; p1 += qb1;
            if (p0 > m0v) {
                float r = __expf(m0v - p0); m0v = p0; l0v = fmaf(l0v, r, 1.f);
#pragma unroll
                for (int i = 0; i < 16; i++) acc0[i] = fmaf(acc0[i], r, tv[i]);
            } else {
                float e = __expf(p0 - m0v); l0v += e;
#pragma unroll
                for (int i = 0; i < 16; i++) acc0[i] = fmaf(e, tv[i], acc0[i]);
            }
            if (p1 > m1v) {
                float r = __expf(m1v - p1); m1v = p1; l1v = fmaf(l1v, r, 1.f);
#pragma unroll
                for (int i = 0; i < 16; i++) acc1[i] = fmaf(acc1[i], r, tv[i]);
            } else {
                float e = __expf(p1 - m1v); l1v += e;
#pragma unroll
                for (int i = 0; i < 16; i++) acc1[i] = fmaf(e, tv[i], acc1[i]);
            }
        }
    }
    if (lane == 0) {
        g_ml[2*(ob+h0)] = m0v; g_ml[2*(ob+h0)+1] = l0v;
        g_ml[2*(ob+h1)] = m1v; g_ml[2*(ob+h1)+1] = l1v;
    }
    float* a0 = g_acc + (size_t)(ob + h0) * 512;
    float* a1 = g_acc + (size_t)(ob + h1) * 512;
#pragma unroll
    for (int j = 0; j < 4; j++) {
        *(float4*)&a0[lane*16 + j*4] = make_float4(acc0[j*4], acc0[j*4+1], acc0[j*4+2], acc0[j*4+3]);
        *(float4*)&a1[lane*16 + j*4] = make_float4(acc1[j*4], acc1[j*4+1], acc1[j*4+2], acc1[j*4+3]);
    }
}

// ====== combine: log-sum-exp merge of 8 chunks -> g_u[n*4096 + h*512 + d] ======
__global__ void combine_kernel()
{
    const int b = blockIdx.x;       // n*8 + h
    const int n = b >> 3, h = b & 7;
    float mv[8], lv[8];
    float M = -INFINITY;
#pragma unroll
    for (int c = 0; c < 8; c++) {
        int idx = (n * 8 + c) * 8 + h;
        mv[c] = g_ml[2*idx]; lv[c] = g_ml[2*idx+1];
        M = fmaxf(M, mv[c]);
    }
    float w[8], L = 0.f;
#pragma unroll
    for (int c = 0; c < 8; c++) {
        w[c] = (mv[c] == -INFINITY) ? 0.f : __expf(mv[c] - M);
        L = fmaf(w[c], lv[c], L);
    }
    const float invL = 1.f / L;
    const int d0 = threadIdx.x * 4;
    float4 s = make_float4(0.f, 0.f, 0.f, 0.f);
#pragma unroll
    for (int c = 0; c < 8; c++) {
        if (w[c] != 0.f) {
            float4 a = *(const float4*)&g_acc[(size_t)((n*8+c)*8+h) * 512 + d0];
            s.x = fmaf(w[c], a.x, s.x); s.y = fmaf(w[c], a.y, s.y);
            s.z = fmaf(w[c], a.z, s.z); s.w = fmaf(w[c], a.w, s.w);
        }
    }
    s.x *= invL; s.y *= invL; s.z *= invL; s.w *= invL;
    *(float4*)&g_u[(size_t)(n * 8 + h) * 512 + d0] = s;
}

// ===== out split-K: part[z] = u[128, z*512:(z+1)*512] @ Wvo[z*512:, :512] =====
__global__ void outk_kernel()
{
    __shared__ float As[16][72];
    __shared__ float Bs[16][72];
    const int m0 = blockIdx.x * 64, n0 = blockIdx.y * 64, z = blockIdx.z;
    const int tid = threadIdx.x;
    const int lrA = tid >> 2, lcA = (tid & 3) << 2;
    const int lrB = tid >> 4, lcB = (tid & 15) << 2;
    const int tx = tid & 15, ty = tid >> 4;
    const int kbeg = z * 512;
    float acc[4][4] = {};
    for (int k0 = kbeg; k0 < kbeg + 512; k0 += 16) {
        float4 a4 = *(const float4*)(g_u + (size_t)(m0 + lrA) * 4096 + k0 + lcA);
        As[lcA+0][lrA] = a4.x; As[lcA+1][lrA] = a4.y; As[lcA+2][lrA] = a4.z; As[lcA+3][lrA] = a4.w;
        *(float4*)&Bs[lrB][lcB] = *(const float4*)(g_wvo + (size_t)(k0 + lrB) * 512 + n0 + lcB);
        __syncthreads();
#pragma unroll
        for (int k = 0; k < 16; k++) {
            float4 ar = *(const float4*)&As[k][ty * 4];
            float4 br = *(const float4*)&Bs[k][tx * 4];
            float arr[4] = {ar.x, ar.y, ar.z, ar.w};
            float brr[4] = {br.x, br.y, br.z, br.w};
#pragma unroll
            for (int i = 0; i < 4; i++)
#pragma unroll
                for (int j = 0; j < 4; j++) acc[i][j] = fmaf(arr[i], brr[j], acc[i][j]);
        }
        __syncthreads();
    }
#pragma unroll
    for (int i = 0; i < 4; i++)
#pragma unroll
        for (int j = 0; j < 4; j++)
            g_fc2part[z * 65536 + (m0 + ty * 4 + i) * 512 + n0 + tx * 4 + j] = acc[i][j];
}

__global__ void out_reduce(float* __restrict__ dout)
{
    int i = blockIdx.x * 256 + threadIdx.x;
    float s = g_bout[i & 511];
#pragma unroll
    for (int z = 0; z < 8; z++) s += g_fc2part[z * 65536 + i];
    dout[i] = s;
}

extern "C" void kernel_launch(void* const* d_in, const int* in_sizes, int n_in,
                              void* d_out, int out_size)
{
    const float* v     = (const float*)d_in[0];
    const float* t     = (const float*)d_in[1];
    const int*   t_len = (const int*)  d_in[2];
    const float* W_fc1 = (const float*)d_in[3];
    const float* b_fc1 = (const float*)d_in[4];
    const float* W_fc2 = (const float*)d_in[5];
    const float* b_fc2 = (const float*)d_in[6];
    const float* Wq    = (const float*)d_in[7];
    const float* Wk    = (const float*)d_in[8];
    const float* Wv    = (const float*)d_in[9];
    const float* bq    = (const float*)d_in[10];
    const float* bk    = (const float*)d_in[11];
    const float* bv    = (const float*)d_in[12];
    const float* Wo    = (const float*)d_in[13];
    const float* bo    = (const float*)d_in[14];
    float* out = (float*)d_out;

    float *d_wqT, *d_wvT, *d_woT, *d_wqk, *d_wvo;
    cudaGetSymbolAddress((void**)&d_wqT, g_wqT);
    cudaGetSymbolAddress((void**)&d_wvT, g_wvT);
    cudaGetSymbolAddress((void**)&d_woT, g_woT);
    cudaGetSymbolAddress((void**)&d_wqk, g_wqk);
    cudaGetSymbolAddress((void**)&d_wvo, g_wvo);

    // --- weight-only precomputes ---
    transpose512<<<dim3(16, 16), dim3(32, 8)>>>(Wq, d_wqT);
    transpose512<<<dim3(16, 16), dim3(32, 8)>>>(Wv, d_wvT);
    transpose512<<<dim3(16, 16), dim3(32, 8)>>>(Wo, d_woT);
    prep_gemm<<<dim3(8, 8, 8), 256>>>(d_wqT, Wk,    d_wqk, 4096, 0,   512, SCALE); // Wqk[i, h*512+j]
    prep_gemm<<<dim3(8, 8, 8), 256>>>(d_wvT, d_woT, d_wvo, 512,  512, 0,   1.0f);  // Wvo[h*512+dt, e]
    misc_prep<<<35, 256>>>(Wq, Wk, Wo, bq, bk, bv, bo);

    // --- main pipeline ---
    fc1_kernel<<<dim3(24, 8), 256>>>(v, W_fc1, b_fc1);
    fc2_kernel<<<dim3(2, 8, 8), 256>>>(W_fc2);
    fc2_reduce<<<256, 256>>>(b_fc2, out);                 // vfeat -> out[0:65536]
    qw_kernel<<<dim3(2, 64), 256>>>();                    // qW (replaces q + qW GEMMs)
    qb2_kernel<<<128, 256>>>();
    cudaFuncSetAttribute(flash_kernel, cudaFuncAttributeMaxDynamicSharedMemorySize, FLASH_SMEM);
    flash_kernel<<<dim3(NSPLIT, NB), 128, FLASH_SMEM>>>(t, t_len);
    combine_kernel<<<1024, 128>>>();
    outk_kernel<<<dim3(2, 8, 8), 256>>>();                // u @ Wvo split-K
    out_reduce<<<256, 256>>>(out + 65536);                // attn_out
}